// round 1
// baseline (speedup 1.0000x reference)
#include <cuda_runtime.h>
#include <climits>

// Problem shape (fixed): B=4, C=1, D=64, H=256, W=256
#define SLICES      256          // B*D
#define SPLIT       4            // row-bands per slice
#define NBLOCKS     (SLICES * SPLIT)   // 1024
#define THREADS     256
#define SLICE_ELEMS 65536        // H*W
#define PART_ELEMS  (SLICE_ELEMS / SPLIT)  // 16384
#define PART_F4     (PART_ELEMS / 4)       // 4096
#define TOTAL_ELEMS 16777216.0f
#define NBOX_ELEMS  1024.0f

// Scratch (no allocation allowed) — partials per block
__device__ float g_seg[NBLOCKS];
__device__ int4  g_box[NBLOCKS];   // x=minR, y=maxR, z=minC, w=maxC

__device__ __forceinline__ float softplus_term(float x, float t) {
    // logaddexp(0, x) - x*t  computed stably
    float sp = fmaxf(x, 0.0f) + log1pf(__expf(-fabsf(x)));
    return sp - x * t;
}

__global__ void __launch_bounds__(THREADS) pass1_kernel(
    const float4* __restrict__ x4p, const float4* __restrict__ t4p)
{
    const int blk = blockIdx.x;        // blk = slice*SPLIT + part
    const int tid = threadIdx.x;
    const int part = blk & (SPLIT - 1);
    const int rowBase = part * 64;     // 256 rows / SPLIT

    const float4* __restrict__ xb = x4p + (size_t)blk * PART_F4;
    const float4* __restrict__ tb = t4p + (size_t)blk * PART_F4;

    float seg = 0.0f;
    int minR = INT_MAX, maxR = -1, minC = INT_MAX, maxC = -1;

    // 16 iterations per thread
    #pragma unroll 4
    for (int i = tid; i < PART_F4; i += THREADS) {
        float4 xv = xb[i];
        float4 tv = tb[i];
        int row = rowBase + (i >> 6);        // 64 float4 per 256-wide row
        int colBase = (i & 63) << 2;

        seg += softplus_term(xv.x, tv.x);
        seg += softplus_term(xv.y, tv.y);
        seg += softplus_term(xv.z, tv.z);
        seg += softplus_term(xv.w, tv.w);

        bool p0 = xv.x > 0.0f, p1 = xv.y > 0.0f, p2 = xv.z > 0.0f, p3 = xv.w > 0.0f;
        if (p0 | p1 | p2 | p3) {
            minR = min(minR, row);
            maxR = max(maxR, row);
            int lo = p0 ? 0 : (p1 ? 1 : (p2 ? 2 : 3));
            int hi = p3 ? 3 : (p2 ? 2 : (p1 ? 1 : 0));
            minC = min(minC, colBase + lo);
            maxC = max(maxC, colBase + hi);
        }
    }

    // block reduction
    __shared__ float s_seg[THREADS];
    __shared__ int s_minR[THREADS], s_maxR[THREADS], s_minC[THREADS], s_maxC[THREADS];
    s_seg[tid] = seg;
    s_minR[tid] = minR; s_maxR[tid] = maxR;
    s_minC[tid] = minC; s_maxC[tid] = maxC;
    __syncthreads();
    #pragma unroll
    for (int off = THREADS / 2; off > 0; off >>= 1) {
        if (tid < off) {
            s_seg[tid]  += s_seg[tid + off];
            s_minR[tid]  = min(s_minR[tid], s_minR[tid + off]);
            s_maxR[tid]  = max(s_maxR[tid], s_maxR[tid + off]);
            s_minC[tid]  = min(s_minC[tid], s_minC[tid + off]);
            s_maxC[tid]  = max(s_maxC[tid], s_maxC[tid + off]);
        }
        __syncthreads();
    }
    if (tid == 0) {
        g_seg[blk] = s_seg[0];
        g_box[blk] = make_int4(s_minR[0], s_maxR[0], s_minC[0], s_maxC[0]);
    }
}

__global__ void __launch_bounds__(SLICES) pass2_kernel(
    const float* __restrict__ tgt, float* __restrict__ out)
{
    const int s = threadIdx.x;   // slice index 0..255

    float seg = 0.0f;
    int minR = INT_MAX, maxR = -1, minC = INT_MAX, maxC = -1;
    #pragma unroll
    for (int p = 0; p < SPLIT; ++p) {
        int idx = s * SPLIT + p;
        seg += g_seg[idx];
        int4 b = g_box[idx];
        minR = min(minR, b.x); maxR = max(maxR, b.y);
        minC = min(minC, b.z); maxC = max(maxC, b.w);
    }

    float bx, by, bw, bh;
    if (maxR < 0) {              // empty mask
        bx = 0.0f; by = 0.0f; bw = 256.0f; bh = 256.0f;
    } else {
        bx = (float)minC; by = (float)minR;
        bw = (float)(maxC - minC); bh = (float)(maxR - minR);
    }

    const float* tb = tgt + s * 4;
    float pred[4] = {bx, by, bw, bh};
    float l = 0.0f;
    #pragma unroll
    for (int j = 0; j < 4; ++j) {
        float d = pred[j] - tb[j];
        float ad = fabsf(d);
        l += (ad < 1.0f) ? 0.5f * d * d : ad - 0.5f;
    }

    __shared__ float s_seg[SLICES];
    __shared__ float s_box[SLICES];
    s_seg[s] = seg;
    s_box[s] = l;
    __syncthreads();
    #pragma unroll
    for (int off = SLICES / 2; off > 0; off >>= 1) {
        if (s < off) {
            s_seg[s] += s_seg[s + off];
            s_box[s] += s_box[s + off];
        }
        __syncthreads();
    }
    if (s == 0) {
        out[0] = s_seg[0] / TOTAL_ELEMS;
        out[1] = s_box[0] / NBOX_ELEMS;
    }
}

extern "C" void kernel_launch(void* const* d_in, const int* in_sizes, int n_in,
                              void* d_out, int out_size)
{
    const float4* x4 = (const float4*)d_in[0];   // model_output
    const float4* t4 = (const float4*)d_in[1];   // target_masks
    const float*  tb = (const float*)d_in[2];    // target_bboxes
    float* out = (float*)d_out;

    pass1_kernel<<<NBLOCKS, THREADS>>>(x4, t4);
    pass2_kernel<<<1, SLICES>>>(tb, out);
}

// round 2
// speedup vs baseline: 1.2329x; 1.2329x over previous
#include <cuda_runtime.h>
#include <climits>

// Problem shape (fixed): B=4, C=1, D=64, H=256, W=256
#define SLICES      256                // B*D
#define SPLIT       4                  // row-bands per slice
#define NBLOCKS     (SLICES * SPLIT)   // 1024
#define THREADS     256
#define SLICE_ELEMS 65536              // H*W
#define PART_ELEMS  (SLICE_ELEMS / SPLIT)  // 16384
#define PART_F4     (PART_ELEMS / 4)       // 4096
#define TOTAL_ELEMS 16777216.0f
#define NBOX_ELEMS  1024.0f

// Scratch (no allocation allowed) — partials per block
__device__ float        g_seg[NBLOCKS];
__device__ int4         g_box[NBLOCKS];   // x=minR, y=maxR, z=minC, w=maxC
__device__ unsigned int g_count = 0;

__device__ __forceinline__ float softplus_term(float x, float t) {
    // logaddexp(0, x) - x*t, stable & branch-free:
    //   max(x,0) + log(1 + exp(-|x|)) - x*t
    float e  = __expf(-fabsf(x));
    float sp = fmaxf(x, 0.0f) + __logf(1.0f + e);
    return __fmaf_rn(-x, t, sp);
}

__global__ void __launch_bounds__(THREADS) fused_kernel(
    const float4* __restrict__ x4p, const float4* __restrict__ t4p,
    const float*  __restrict__ tgt, float* __restrict__ out)
{
    const int blk  = blockIdx.x;       // blk = slice*SPLIT + part
    const int tid  = threadIdx.x;
    const int part = blk & (SPLIT - 1);
    const int rowBase = part * 64;     // 256 rows / SPLIT

    const float4* __restrict__ xb = x4p + (size_t)blk * PART_F4;
    const float4* __restrict__ tb = t4p + (size_t)blk * PART_F4;

    float seg = 0.0f;
    int minR = INT_MAX, maxR = -1, minC = INT_MAX, maxC = -1;

    #pragma unroll 4
    for (int i = tid; i < PART_F4; i += THREADS) {
        float4 xv = xb[i];
        float4 tv = tb[i];
        int row     = rowBase + (i >> 6);   // 64 float4 per 256-wide row
        int colBase = (i & 63) << 2;

        seg += softplus_term(xv.x, tv.x);
        seg += softplus_term(xv.y, tv.y);
        seg += softplus_term(xv.z, tv.z);
        seg += softplus_term(xv.w, tv.w);

        bool p0 = xv.x > 0.0f, p1 = xv.y > 0.0f, p2 = xv.z > 0.0f, p3 = xv.w > 0.0f;
        if (p0 | p1 | p2 | p3) {
            minR = min(minR, row);
            maxR = max(maxR, row);
            int lo = p0 ? 0 : (p1 ? 1 : (p2 ? 2 : 3));
            int hi = p3 ? 3 : (p2 ? 2 : (p1 ? 1 : 0));
            minC = min(minC, colBase + lo);
            maxC = max(maxC, colBase + hi);
        }
    }

    // ---- intra-warp reduction (shuffle) ----
    #pragma unroll
    for (int off = 16; off > 0; off >>= 1) {
        seg  += __shfl_xor_sync(0xFFFFFFFFu, seg,  off);
        minR  = min(minR, __shfl_xor_sync(0xFFFFFFFFu, minR, off));
        maxR  = max(maxR, __shfl_xor_sync(0xFFFFFFFFu, maxR, off));
        minC  = min(minC, __shfl_xor_sync(0xFFFFFFFFu, minC, off));
        maxC  = max(maxC, __shfl_xor_sync(0xFFFFFFFFu, maxC, off));
    }

    // ---- cross-warp reduction via smem (8 warps) ----
    __shared__ float s_seg[8];
    __shared__ int   s_mnR[8], s_mxR[8], s_mnC[8], s_mxC[8];
    const int wid = tid >> 5, lid = tid & 31;
    if (lid == 0) {
        s_seg[wid] = seg;
        s_mnR[wid] = minR; s_mxR[wid] = maxR;
        s_mnC[wid] = minC; s_mxC[wid] = maxC;
    }
    __syncthreads();
    if (tid == 0) {
        float rs = s_seg[0];
        int rmnR = s_mnR[0], rmxR = s_mxR[0], rmnC = s_mnC[0], rmxC = s_mxC[0];
        #pragma unroll
        for (int w = 1; w < 8; ++w) {
            rs   += s_seg[w];
            rmnR  = min(rmnR, s_mnR[w]); rmxR = max(rmxR, s_mxR[w]);
            rmnC  = min(rmnC, s_mnC[w]); rmxC = max(rmxC, s_mxC[w]);
        }
        g_seg[blk] = rs;
        g_box[blk] = make_int4(rmnR, rmxR, rmnC, rmxC);
    }

    // ---- last-block-finishes tail ----
    __shared__ bool s_isLast;
    __threadfence();
    if (tid == 0) {
        unsigned int c = atomicAdd(&g_count, 1u);
        s_isLast = (c == NBLOCKS - 1);
    }
    __syncthreads();
    if (!s_isLast) return;

    // Tail: thread s handles slice s (256 threads)
    const int s = tid;
    float segT = 0.0f;
    int mnR = INT_MAX, mxR = -1, mnC = INT_MAX, mxC = -1;
    #pragma unroll
    for (int p = 0; p < SPLIT; ++p) {
        int idx = s * SPLIT + p;
        segT += __ldcg(&g_seg[idx]);
        int4 b = __ldcg(&g_box[idx]);
        mnR = min(mnR, b.x); mxR = max(mxR, b.y);
        mnC = min(mnC, b.z); mxC = max(mxC, b.w);
    }

    float bx, by, bw, bh;
    if (mxR < 0) {                       // empty mask
        bx = 0.0f; by = 0.0f; bw = 256.0f; bh = 256.0f;
    } else {
        bx = (float)mnC; by = (float)mnR;
        bw = (float)(mxC - mnC); bh = (float)(mxR - mnR);
    }

    float pred[4] = {bx, by, bw, bh};
    float l = 0.0f;
    #pragma unroll
    for (int j = 0; j < 4; ++j) {
        float d  = pred[j] - tgt[s * 4 + j];
        float ad = fabsf(d);
        l += (ad < 1.0f) ? 0.5f * d * d : ad - 0.5f;
    }

    // reduce 256 lanes: warp shuffle + smem
    #pragma unroll
    for (int off = 16; off > 0; off >>= 1) {
        segT += __shfl_xor_sync(0xFFFFFFFFu, segT, off);
        l    += __shfl_xor_sync(0xFFFFFFFFu, l,    off);
    }
    __shared__ float t_seg[8], t_box[8];
    const int wid2 = tid >> 5, lid2 = tid & 31;
    if (lid2 == 0) { t_seg[wid2] = segT; t_box[wid2] = l; }
    __syncthreads();
    if (tid == 0) {
        float fs = 0.0f, fb = 0.0f;
        #pragma unroll
        for (int w = 0; w < 8; ++w) { fs += t_seg[w]; fb += t_box[w]; }
        out[0] = fs / TOTAL_ELEMS;
        out[1] = fb / NBOX_ELEMS;
        g_count = 0;                     // reset for next graph replay
    }
}

extern "C" void kernel_launch(void* const* d_in, const int* in_sizes, int n_in,
                              void* d_out, int out_size)
{
    const float4* x4 = (const float4*)d_in[0];   // model_output
    const float4* t4 = (const float4*)d_in[1];   // target_masks
    const float*  tb = (const float*)d_in[2];    // target_bboxes
    float* out = (float*)d_out;

    fused_kernel<<<NBLOCKS, THREADS>>>(x4, t4, tb, out);
}